// round 3
// baseline (speedup 1.0000x reference)
#include <cuda_runtime.h>
#include <cuda_bf16.h>

// ---------------------------------------------------------------------------
// CutsSelector collapsed to scalar-per-node form, fused into ONE persistent
// kernel with software grid barriers:
//   v = f2@cls ; u = f1@cls ; p = Wd@v ; q = Ws@v
//   r = we.v ; s = g_b.v ; c0 = f_b.cls + cls_b
//   t[n]=x[n].q ; du[n]=x[n].u ; dp[n]=x[n].p
//   {acc,cnt}[dst] += {t[src] + r*ea, 1}   (one red.global.add.v2.f32 / edge)
//   score = du + c0 + (cnt>0 ? dp + acc/cnt + s : 0) ; probs = sigmoid(score)
// ---------------------------------------------------------------------------

#define C 128
#define NODE_CAP 24576
#define NBLK 128
#define NTHR 1024

__device__ float  g_vec_u[C];
__device__ float  g_vec_p[C];
__device__ float  g_vec_q[C];
__device__ float  g_scalar_r;
__device__ float  g_scalar_s;
__device__ float  g_scalar_c0;
__device__ float  g_t[NODE_CAP];
__device__ float  g_du[NODE_CAP];
__device__ float  g_dp[NODE_CAP];
__device__ float2 g_accnt[NODE_CAP];
__device__ unsigned g_bar;    // zero-initialized; reset by last block each run
__device__ unsigned g_done;
__device__ float  g_sink;     // DCE-prevention for prefetch (never written)

__device__ __forceinline__ float warp_sum(float v) {
    #pragma unroll
    for (int o = 16; o > 0; o >>= 1) v += __shfl_xor_sync(0xffffffffu, v, o);
    return v;
}

// Software grid barrier: all blocks resident (grid <= #SMs), so spin is safe.
__device__ __forceinline__ void grid_barrier(unsigned target) {
    __syncthreads();
    if (threadIdx.x == 0) {
        __threadfence();
        atomicAdd(&g_bar, 1u);
        unsigned v;
        do {
            asm volatile("ld.global.acquire.gpu.u32 %0, [%1];"
                         : "=r"(v) : "l"(&g_bar));
        } while (v < target);
    }
    __syncthreads();
}

__global__ void __launch_bounds__(NTHR, 1)
fused_kernel(const float* __restrict__ x,
             const void*  __restrict__ eidx,
             const float* __restrict__ ea,
             const float* __restrict__ g_w,   // [257,128]
             const float* __restrict__ g_b,   // [128]
             const float* __restrict__ f_w,   // [256,128]
             const float* __restrict__ f_b,   // [128]
             const float* __restrict__ cls_w, // [128]
             const float* __restrict__ cls_b, // [1]
             float* __restrict__ out,
             int N, long long E, int twopart)
{
    const int tid  = threadIdx.x;
    const int bid  = blockIdx.x;
    const int nblk = gridDim.x;
    const int wi   = tid >> 5;
    const int lane = tid & 31;
    const long long gtid       = (long long)bid * NTHR + tid;
    const long long totThreads = (long long)nblk * NTHR;

    __shared__ float scls[C], sv[C], su[C], sp[C], sq[C];
    __shared__ int   s_is64;

    // ---- index-dtype sniff (per block, warp 0): int64 nonneg < 2^31 shows
    //      zeros at every odd int32 position ----
    if (wi == 0) {
        const int* p = (const int*)eidx;
        int ok = (p[2 * lane + 1] == 0) &&
                 (p[2 * (lane + 32) + 1] == 0) &&
                 (p[2 * (lane + 64) + 1] == 0);
        unsigned b = __ballot_sync(0xffffffffu, ok);
        if (lane == 0) s_is64 = (b == 0xffffffffu) ? 1 : 0;
    }

    // =========================== PHASE 0 ====================================
    if (bid == 0) {
        // Block 0: all the tiny matvecs (32 warps, ILP'd loads).
        if (tid < C) scls[tid] = cls_w[tid];
        __syncthreads();
        float4 cc = ((const float4*)scls)[lane];

        float4 a[8];
        // Stage 1: 256 dots of f_w rows with cls_w -> u (rows 0..127), v (128..255)
        #pragma unroll
        for (int j = 0; j < 8; j++)
            a[j] = ((const float4*)(f_w + (size_t)(wi * 8 + j) * C))[lane];
        #pragma unroll
        for (int j = 0; j < 8; j++) {
            float part = warp_sum(a[j].x * cc.x + a[j].y * cc.y +
                                  a[j].z * cc.z + a[j].w * cc.w);
            if (lane == 0) {
                int d = wi * 8 + j;
                if (d < C) { g_vec_u[d] = part; su[d] = part; }
                else       { sv[d - C]  = part; }
            }
        }
        __syncthreads();
        float4 vv = ((const float4*)sv)[lane];

        // Stage 2: 256 dots of g_w rows with v -> p (rows 0..127), q (128..255)
        #pragma unroll
        for (int j = 0; j < 8; j++)
            a[j] = ((const float4*)(g_w + (size_t)(wi * 8 + j) * C))[lane];
        #pragma unroll
        for (int j = 0; j < 8; j++) {
            float part = warp_sum(a[j].x * vv.x + a[j].y * vv.y +
                                  a[j].z * vv.z + a[j].w * vv.w);
            if (lane == 0) {
                int d = wi * 8 + j;
                if (d < C) { g_vec_p[d] = part; sp[d] = part; }
                else       { g_vec_q[d - C] = part; sq[d - C] = part; }
            }
        }
        __syncthreads();

        // Stage 3: scalars r, s, c0 (warp 0)
        if (wi == 0) {
            float r = 0.f, s = 0.f, c = 0.f;
            #pragma unroll
            for (int k = lane; k < C; k += 32) {
                float vk = sv[k];
                r += g_w[2 * C * C + k] * vk;
                s += g_b[k] * vk;
                c += f_b[k] * scls[k];
            }
            r = warp_sum(r); s = warp_sum(s); c = warp_sum(c);
            if (lane == 0) {
                g_scalar_r  = r;
                g_scalar_s  = s;
                g_scalar_c0 = c + cls_b[0];
            }
        }
    } else {
        // Blocks 1..: zero accumulators + prefetch x into L2.
        const long long pth = (long long)(nblk - 1) * NTHR;
        const long long pid = (long long)(bid - 1) * NTHR + tid;
        for (long long n = pid; n < N; n += pth)
            g_accnt[n] = make_float2(0.f, 0.f);

        const float4* x4 = (const float4*)x;
        const long long nx4 = (long long)N * (C / 4);
        float acc = 0.f;
        for (long long i = pid; i < nx4; i += pth) {
            float4 t = __ldcg(&x4[i]);
            acc += t.x + t.y + t.z + t.w;
        }
        if (__float_as_uint(acc) == 0xDEADBEEFu) g_sink = acc;  // keep loads
    }

    grid_barrier((unsigned)nblk);

    // =========================== PHASE 1: t / du / dp =======================
    if (bid != 0) {
        if (tid < C) {
            su[tid] = g_vec_u[tid];
            sp[tid] = g_vec_p[tid];
            sq[tid] = g_vec_q[tid];
        }
    }
    __syncthreads();
    {
        float4 qv = ((const float4*)sq)[lane];
        float4 uv = ((const float4*)su)[lane];
        float4 pv = ((const float4*)sp)[lane];
        const int totalWarps = nblk * (NTHR / 32);
        const int gwarp = bid * (NTHR / 32) + wi;
        for (int node = gwarp; node < N; node += totalWarps) {
            float4 xv = __ldg((const float4*)(x + (size_t)node * C) + lane);
            float dq = xv.x * qv.x + xv.y * qv.y + xv.z * qv.z + xv.w * qv.w;
            float du = xv.x * uv.x + xv.y * uv.y + xv.z * uv.z + xv.w * uv.w;
            float dp = xv.x * pv.x + xv.y * pv.y + xv.z * pv.z + xv.w * pv.w;
            #pragma unroll
            for (int o = 16; o > 0; o >>= 1) {
                dq += __shfl_xor_sync(0xffffffffu, dq, o);
                du += __shfl_xor_sync(0xffffffffu, du, o);
                dp += __shfl_xor_sync(0xffffffffu, dp, o);
            }
            if (lane == 0) {
                g_t[node]  = dq;
                g_du[node] = du;
                g_dp[node] = dp;
            }
        }
    }

    grid_barrier(2u * nblk);

    // =========================== PHASE 2: edges =============================
    {
        const float rs = g_scalar_r;
        const long long half = E >> 1;
        if (s_is64) {
            const longlong2* p0 = (const longlong2*)eidx;
            const longlong2* p1 = (const longlong2*)((const long long*)eidx + E);
            const float2*    a2 = (const float2*)ea;
            for (long long i = gtid; i < half; i += totThreads) {
                longlong2 sr = p0[i];
                longlong2 ds = p1[i];
                float2    e2 = a2[i];
                float v0 = __ldg(&g_t[sr.x]) + e2.x * rs;
                float v1 = __ldg(&g_t[sr.y]) + e2.y * rs;
                asm volatile("red.global.add.v2.f32 [%0], {%1, %2};"
                             :: "l"(&g_accnt[ds.x]), "f"(v0), "f"(1.0f) : "memory");
                asm volatile("red.global.add.v2.f32 [%0], {%1, %2};"
                             :: "l"(&g_accnt[ds.y]), "f"(v1), "f"(1.0f) : "memory");
            }
            if ((E & 1) && gtid == 0) {
                const long long* p = (const long long*)eidx;
                long long src = p[E - 1], dst = p[2 * E - 1];
                float v = __ldg(&g_t[src]) + ea[E - 1] * rs;
                asm volatile("red.global.add.v2.f32 [%0], {%1, %2};"
                             :: "l"(&g_accnt[dst]), "f"(v), "f"(1.0f) : "memory");
            }
        } else {
            const int2*   p0 = (const int2*)eidx;
            const int2*   p1 = (const int2*)((const int*)eidx + E);
            const float2* a2 = (const float2*)ea;
            for (long long i = gtid; i < half; i += totThreads) {
                int2   sr = p0[i];
                int2   ds = p1[i];
                float2 e2 = a2[i];
                float v0 = __ldg(&g_t[sr.x]) + e2.x * rs;
                float v1 = __ldg(&g_t[sr.y]) + e2.y * rs;
                asm volatile("red.global.add.v2.f32 [%0], {%1, %2};"
                             :: "l"(&g_accnt[ds.x]), "f"(v0), "f"(1.0f) : "memory");
                asm volatile("red.global.add.v2.f32 [%0], {%1, %2};"
                             :: "l"(&g_accnt[ds.y]), "f"(v1), "f"(1.0f) : "memory");
            }
            if ((E & 1) && gtid == 0) {
                const int* p = (const int*)eidx;
                int src = p[E - 1], dst = p[2 * E - 1];
                float v = __ldg(&g_t[src]) + ea[E - 1] * rs;
                asm volatile("red.global.add.v2.f32 [%0], {%1, %2};"
                             :: "l"(&g_accnt[dst]), "f"(v), "f"(1.0f) : "memory");
            }
        }
    }

    grid_barrier(3u * nblk);

    // =========================== PHASE 3: output ============================
    {
        const float ss = g_scalar_s;
        const float c0 = g_scalar_c0;
        for (long long n = gtid; n < N; n += totThreads) {
            float2 ac = __ldcg(&g_accnt[n]);
            float du  = __ldcg(&g_du[n]);
            float dp  = __ldcg(&g_dp[n]);
            float score = du + c0;
            if (ac.y > 0.f) score += dp + ac.x / ac.y + ss;
            float pr = 1.0f / (1.0f + expf(-score));
            if (twopart) {
                out[n]     = (pr > 0.5f) ? 1.0f : 0.0f;
                out[N + n] = pr;
            } else {
                out[n] = pr;
            }
        }
    }

    // ---- completion: last block resets the barrier counters for the next
    //      graph replay ----
    __syncthreads();
    if (tid == 0) {
        __threadfence();
        unsigned old = atomicAdd(&g_done, 1u);
        if (old == (unsigned)nblk - 1u) {
            g_bar  = 0u;
            g_done = 0u;
            __threadfence();
        }
    }
}

extern "C" void kernel_launch(void* const* d_in, const int* in_sizes, int n_in,
                              void* d_out, int out_size) {
    // metadata order: x_a, edge_index, edge_attr, g_w, g_b, f_w, f_b, cls_w, cls_b
    const float* x_a        = (const float*)d_in[0];
    const void*  edge_index =               d_in[1];
    const float* edge_attr  = (const float*)d_in[2];
    const float* g_w        = (const float*)d_in[3];
    const float* g_b        = (const float*)d_in[4];
    const float* f_w        = (const float*)d_in[5];
    const float* f_b        = (const float*)d_in[6];
    const float* cls_w      = (const float*)d_in[7];
    const float* cls_b      = (const float*)d_in[8];
    float* out = (float*)d_out;

    const int       N = in_sizes[0] / C;        // 20000
    const long long E = (long long)in_sizes[2]; // 640000
    const int twopart = (out_size >= 2 * N) ? 1 : 0;

    fused_kernel<<<NBLK, NTHR>>>(x_a, edge_index, edge_attr,
                                 g_w, g_b, f_w, f_b, cls_w, cls_b,
                                 out, N, E, twopart);
}